// round 2
// baseline (speedup 1.0000x reference)
#include <cuda_runtime.h>

#define NA   3
#define NC   20
#define NCH  25      // 5 + NC
#define NT   256     // number of targets
#define EPSF 1e-7f

// Accumulators. Zero-initialized at module load (first call); finalize_kernel
// re-zeroes them after reading so every graph replay starts clean.
__device__ double g_obj_sum[3];
__device__ float  g_corr[3];
__device__ float  g_box;
__device__ float  g_cls;

__device__ __forceinline__ float softplusf(float x) {
    // stable: max(x,0) + log1p(exp(-|x|))
    return fmaxf(x, 0.f) + log1pf(__expf(-fabsf(x)));
}
__device__ __forceinline__ float sigmoidf(float x) {
    return 1.f / (1.f + __expf(-x));
}

__device__ __forceinline__ float blockReduceSum256(float v, float* sh) {
    int t = threadIdx.x;
    sh[t] = v;
    __syncthreads();
    #pragma unroll
    for (int s = 128; s > 0; s >>= 1) {
        if (t < s) sh[t] += sh[t + s];
        __syncthreads();
    }
    float r = sh[0];
    __syncthreads();
    return r;
}

__global__ void __launch_bounds__(256) main_kernel(
    const float* __restrict__ p0,
    const float* __restrict__ p1,
    const float* __restrict__ p2,
    const float* __restrict__ tg)
{
    const int bid = blockIdx.x;
    const int t   = threadIdx.x;

    if (bid < 9) {
        // ---------------- target blocks: (scale, anchor) ----------------
        __shared__ float s_t[NT * 6];
        __shared__ float sh[NT];
        for (int i = t; i < NT * 6; i += 256) s_t[i] = tg[i];
        __syncthreads();

        const int s = bid / 3;
        const int a = bid - 3 * s;
        const int H  = (s == 0) ? 80 : (s == 1) ? 40 : 20;
        const int W  = H;
        const int HW = H * W;
        const float* p = (s == 0) ? p0 : (s == 1) ? p1 : p2;
        const float fw = (float)W, fh = (float)H;

        const int n = t;  // one thread per target
        const int   bi = (int)s_t[n * 6 + 0];
        const int   ci = (int)s_t[n * 6 + 1];
        const float cx = s_t[n * 6 + 2];
        const float cy = s_t[n * 6 + 3];
        const float tw = s_t[n * 6 + 4];
        const float th = s_t[n * 6 + 5];

        const int gi = (int)fminf(fmaxf(cx * fw, 0.f), fw - 1.f);
        const int gj = (int)fminf(fmaxf(cy * fh, 0.f), fh - 1.f);

        const float* cellp = p + ((size_t)(bi * NA * NCH + a * NCH)) * HW
                               + (size_t)gj * W + gi;

        const float sx = sigmoidf(cellp[0]);
        const float sy = sigmoidf(cellp[HW]);

        const float twh = tw * fw * 0.5f;
        const float thh = th * fh * 0.5f;
        const float gif = (float)gi, gjf = (float)gj;

        const float px1 = (sx + gif - twh) / fw;
        const float py1 = (sy + gjf - thh) / fh;
        const float px2 = (sx + gif + twh) / fw;
        const float py2 = (sy + gjf + thh) / fh;

        const float tx1 = cx - tw * 0.5f;
        const float ty1 = cy - th * 0.5f;
        const float tx2 = cx + tw * 0.5f;
        const float ty2 = cy + th * 0.5f;

        // CIoU loss (full formula to match reference bit-for-bit semantics)
        const float ix1 = fmaxf(px1, tx1), iy1 = fmaxf(py1, ty1);
        const float ix2 = fminf(px2, tx2), iy2 = fminf(py2, ty2);
        const float inter  = fmaxf(ix2 - ix1, 0.f) * fmaxf(iy2 - iy1, 0.f);
        const float area_p = (px2 - px1) * (py2 - py1);
        const float area_t = (tx2 - tx1) * (ty2 - ty1);
        const float uni = area_p + area_t - inter + EPSF;
        const float iou = inter / uni;
        const float ex1 = fminf(px1, tx1), ey1 = fminf(py1, ty1);
        const float ex2 = fmaxf(px2, tx2), ey2 = fmaxf(py2, ty2);
        const float c2  = (ex2 - ex1) * (ex2 - ex1) + (ey2 - ey1) * (ey2 - ey1) + EPSF;
        const float dxc = (px1 + px2) * 0.5f - (tx1 + tx2) * 0.5f;
        const float dyc = (py1 + py2) * 0.5f - (ty1 + ty2) * 0.5f;
        const float rho2 = dxc * dxc + dyc * dyc;
        const float pw  = fmaxf(px2 - px1, EPSF);
        const float ph  = fmaxf(py2 - py1, EPSF);
        const float twc = fmaxf(tx2 - tx1, EPSF);
        const float thc = fmaxf(ty2 - ty1, EPSF);
        const float dd  = atanf(twc / thc) - atanf(pw / ph);
        const float v   = 0.4052847345693511f * dd * dd;   // 4/pi^2
        const float alpha = v / (1.f - iou + v + EPSF);
        const float lbox  = 1.f - (iou - rho2 / c2 - alpha * v);

        // cls BCE: mean_c [softplus(x_c) - y_c * x_c]
        float csum = 0.f;
        #pragma unroll
        for (int c = 0; c < NC; c++) csum += softplusf(cellp[(size_t)(5 + c) * HW]);
        csum = (csum - cellp[(size_t)(5 + ci) * HW]) * (1.f / (float)NC);

        float rb = blockReduceSum256(lbox, sh);
        float rc = blockReduceSum256(csum, sh);
        if (t == 0) {
            atomicAdd(&g_box, rb);
            atomicAdd(&g_cls, rc);
        }

        // obj correction: -x for each UNIQUE target cell, all 3 anchors.
        // Only a==0 blocks do this (uniform branch per block).
        if (a == 0) {
            bool uniq = true;
            for (int m = 0; m < n; m++) {
                if ((int)s_t[m * 6 + 0] != bi) continue;
                int gim = (int)fminf(fmaxf(s_t[m * 6 + 2] * fw, 0.f), fw - 1.f);
                if (gim != gi) continue;
                int gjm = (int)fminf(fmaxf(s_t[m * 6 + 3] * fh, 0.f), fh - 1.f);
                if (gjm == gj) { uniq = false; break; }
            }
            float corr = 0.f;
            if (uniq) {
                const float* op = p + ((size_t)(bi * NA * NCH)) * HW
                                    + (size_t)gj * W + gi;
                corr = -(op[(size_t)4 * HW]
                       + op[(size_t)(NCH + 4) * HW]
                       + op[(size_t)(2 * NCH + 4) * HW]);
            }
            float rcor = blockReduceSum256(corr, sh);
            if (t == 0) atomicAdd(&g_corr[s], rcor);
        }
    } else {
        // ---------------- objectness softplus sweep (float4) ----------------
        __shared__ float ssum[3];
        if (t < 3) ssum[t] = 0.f;
        __syncthreads();

        const int idx = (bid - 9) * 256 + t;
        const int N40 = 153600;   // 614400/4 (scale 0 float4 count)
        const int N41 = 38400;    // 153600/4
        const int N42 = 9600;     // 38400/4
        if (idx < N40 + N41 + N42) {
            int sc, e4, HW4;
            const float* p;
            if (idx < N40)            { sc = 0; p = p0; e4 = idx;             HW4 = 1600; }
            else if (idx < N40 + N41) { sc = 1; p = p1; e4 = idx - N40;       HW4 = 400;  }
            else                      { sc = 2; p = p2; e4 = idx - N40 - N41; HW4 = 100;  }
            const int plane = e4 / HW4;
            const int r     = e4 - plane * HW4;
            const int b     = plane / 3;
            const int a     = plane - 3 * b;
            const float4* q = (const float4*)p
                            + (size_t)(b * (NA * NCH) + a * NCH + 4) * HW4 + r;
            float4 vv = *q;
            float acc = softplusf(vv.x) + softplusf(vv.y)
                      + softplusf(vv.z) + softplusf(vv.w);
            atomicAdd(&ssum[sc], acc);
        }
        __syncthreads();
        if (t < 3 && ssum[t] != 0.f)
            atomicAdd(&g_obj_sum[t], (double)ssum[t]);
    }
}

__global__ void finalize_kernel(float* __restrict__ out, int out_size) {
    if (threadIdx.x == 0 && blockIdx.x == 0) {
        const double cnt[3] = {614400.0, 153600.0, 38400.0};
        double lod = 0.0;
        for (int s = 0; s < 3; s++)
            lod += (g_obj_sum[s] + (double)g_corr[s]) / cnt[s];
        const float lo = (float)lod;
        const float lb = g_box * (1.f / 2304.f);   // N*A*3 = 256*3*3
        const float lc = g_cls * (1.f / 2304.f);
        const float total = 0.05f * lb + 1.0f * lo + 0.5f * lc;
        float vals[5] = {total, lb, lo, lc, 0.f};
        for (int i = 0; i < out_size; i++)
            out[i] = (i < 5) ? vals[i] : 0.f;
        // reset accumulators for the next (graph-replayed) invocation
        g_box = 0.f;
        g_cls = 0.f;
        for (int s = 0; s < 3; s++) { g_corr[s] = 0.f; g_obj_sum[s] = 0.0; }
    }
}

extern "C" void kernel_launch(void* const* d_in, const int* in_sizes, int n_in,
                              void* d_out, int out_size) {
    const float* p0 = (const float*)d_in[0];
    const float* p1 = (const float*)d_in[1];
    const float* p2 = (const float*)d_in[2];
    const float* tg = (const float*)d_in[3];
    (void)in_sizes; (void)n_in;

    // 9 target blocks + 788 objectness blocks (ceil(201600/256))
    main_kernel<<<797, 256>>>(p0, p1, p2, tg);
    finalize_kernel<<<1, 32>>>((float*)d_out, out_size);
}

// round 3
// speedup vs baseline: 1.0370x; 1.0370x over previous
#include <cuda_runtime.h>

#define NA   3
#define NC   20
#define NCH  25      // 5 + NC
#define NT   256     // number of targets
#define EPSF 1e-7f

// Accumulators. Zero-initialized at module load; the finalizing block
// re-zeroes them so every graph replay starts clean.
__device__ double   g_obj_sum[3];
__device__ float    g_corr[3];
__device__ float    g_box;
__device__ float    g_cls;
__device__ unsigned g_done;

__device__ __forceinline__ float sigmoidf(float x) {
    return 1.f / (1.f + __expf(-x));
}

__device__ __forceinline__ float blockReduceSum256(float v, float* sh) {
    int t = threadIdx.x;
    sh[t] = v;
    __syncthreads();
    #pragma unroll
    for (int s = 128; s > 0; s >>= 1) {
        if (t < s) sh[t] += sh[t + s];
        __syncthreads();
    }
    float r = sh[0];
    __syncthreads();
    return r;
}

// one (1 + e^{-|x|}) factor; caller multiplies these and takes a single log
__device__ __forceinline__ float spl_factor(float x) {
    return 1.f + __expf(-fabsf(x));
}

__global__ void __launch_bounds__(256) fused_kernel(
    const float* __restrict__ p0,
    const float* __restrict__ p1,
    const float* __restrict__ p2,
    const float* __restrict__ tg,
    float* __restrict__ out, int out_size)
{
    const int bid = blockIdx.x;
    const int t   = threadIdx.x;

    if (bid < 9) {
        // ---------------- target blocks: (scale, anchor) ----------------
        __shared__ float s_t[NT * 6];
        __shared__ float sh[NT];
        for (int i = t; i < NT * 6; i += 256) s_t[i] = tg[i];
        __syncthreads();

        const int s = bid / 3;
        const int a = bid - 3 * s;
        const int H  = (s == 0) ? 80 : (s == 1) ? 40 : 20;
        const int W  = H;
        const int HW = H * W;
        const float* p = (s == 0) ? p0 : (s == 1) ? p1 : p2;
        const float fw = (float)W, fh = (float)H;

        const int n = t;  // one thread per target
        const int   bi = (int)s_t[n * 6 + 0];
        const int   ci = (int)s_t[n * 6 + 1];
        const float cx = s_t[n * 6 + 2];
        const float cy = s_t[n * 6 + 3];
        const float tw = s_t[n * 6 + 4];
        const float th = s_t[n * 6 + 5];

        const int gi = (int)fminf(fmaxf(cx * fw, 0.f), fw - 1.f);
        const int gj = (int)fminf(fmaxf(cy * fh, 0.f), fh - 1.f);

        const float* cellp = p + ((size_t)(bi * NA * NCH + a * NCH)) * HW
                               + (size_t)gj * W + gi;

        const float sx = sigmoidf(cellp[0]);
        const float sy = sigmoidf(cellp[HW]);

        const float twh = tw * fw * 0.5f;
        const float thh = th * fh * 0.5f;
        const float gif = (float)gi, gjf = (float)gj;

        const float px1 = (sx + gif - twh) / fw;
        const float py1 = (sy + gjf - thh) / fh;
        const float px2 = (sx + gif + twh) / fw;
        const float py2 = (sy + gjf + thh) / fh;

        const float tx1 = cx - tw * 0.5f;
        const float ty1 = cy - th * 0.5f;
        const float tx2 = cx + tw * 0.5f;
        const float ty2 = cy + th * 0.5f;

        // CIoU loss
        const float ix1 = fmaxf(px1, tx1), iy1 = fmaxf(py1, ty1);
        const float ix2 = fminf(px2, tx2), iy2 = fminf(py2, ty2);
        const float inter  = fmaxf(ix2 - ix1, 0.f) * fmaxf(iy2 - iy1, 0.f);
        const float area_p = (px2 - px1) * (py2 - py1);
        const float area_t = (tx2 - tx1) * (ty2 - ty1);
        const float uni = area_p + area_t - inter + EPSF;
        const float iou = inter / uni;
        const float ex1 = fminf(px1, tx1), ey1 = fminf(py1, ty1);
        const float ex2 = fmaxf(px2, tx2), ey2 = fmaxf(py2, ty2);
        const float c2  = (ex2 - ex1) * (ex2 - ex1) + (ey2 - ey1) * (ey2 - ey1) + EPSF;
        const float dxc = (px1 + px2) * 0.5f - (tx1 + tx2) * 0.5f;
        const float dyc = (py1 + py2) * 0.5f - (ty1 + ty2) * 0.5f;
        const float rho2 = dxc * dxc + dyc * dyc;
        const float pw  = fmaxf(px2 - px1, EPSF);
        const float ph  = fmaxf(py2 - py1, EPSF);
        const float twc = fmaxf(tx2 - tx1, EPSF);
        const float thc = fmaxf(ty2 - ty1, EPSF);
        const float dd  = atanf(twc / thc) - atanf(pw / ph);
        const float v   = 0.4052847345693511f * dd * dd;   // 4/pi^2
        const float alpha = v / (1.f - iou + v + EPSF);
        const float lbox  = 1.f - (iou - rho2 / c2 - alpha * v);

        // cls BCE: mean_c [softplus(x_c)] - x_ci/NC  via product-log
        float lin = 0.f, prod = 1.f;
        #pragma unroll
        for (int c = 0; c < NC; c++) {
            float x = cellp[(size_t)(5 + c) * HW];
            lin  += fmaxf(x, 0.f);
            prod *= spl_factor(x);
        }
        float csum = (lin + __logf(prod) - cellp[(size_t)(5 + ci) * HW])
                   * (1.f / (float)NC);

        float rb = blockReduceSum256(lbox, sh);
        float rc = blockReduceSum256(csum, sh);
        if (t == 0) {
            atomicAdd(&g_box, rb);
            atomicAdd(&g_cls, rc);
        }

        // obj correction: -x for each UNIQUE target cell, all 3 anchors.
        if (a == 0) {
            bool uniq = true;
            for (int m = 0; m < n; m++) {
                if ((int)s_t[m * 6 + 0] != bi) continue;
                int gim = (int)fminf(fmaxf(s_t[m * 6 + 2] * fw, 0.f), fw - 1.f);
                if (gim != gi) continue;
                int gjm = (int)fminf(fmaxf(s_t[m * 6 + 3] * fh, 0.f), fh - 1.f);
                if (gjm == gj) { uniq = false; break; }
            }
            float corr = 0.f;
            if (uniq) {
                const float* op = p + ((size_t)(bi * NA * NCH)) * HW
                                    + (size_t)gj * W + gi;
                corr = -(op[(size_t)4 * HW]
                       + op[(size_t)(NCH + 4) * HW]
                       + op[(size_t)(2 * NCH + 4) * HW]);
            }
            float rcor = blockReduceSum256(corr, sh);
            if (t == 0) atomicAdd(&g_corr[s], rcor);
        }
    } else {
        // -------- objectness softplus sweep: 8 elems (2 float4) / thread --------
        __shared__ float ssum[3];
        if (t < 3) ssum[t] = 0.f;
        __syncthreads();

        const int idx = (bid - 9) * 256 + t;   // pair index
        // pairs per scale: 76800 / 19200 / 4800  (total 100800)
        if (idx < 100800) {
            int sc, e8, HW4;
            const float* p;
            if (idx < 76800)      { sc = 0; p = p0; e8 = idx;         HW4 = 1600; }
            else if (idx < 96000) { sc = 1; p = p1; e8 = idx - 76800; HW4 = 400;  }
            else                  { sc = 2; p = p2; e8 = idx - 96000; HW4 = 100;  }
            const int f4    = e8 * 2;
            const int plane = f4 / HW4;          // pair never straddles a plane (HW4 even)
            const int r     = f4 - plane * HW4;
            const int b     = plane / 3;
            const int a     = plane - 3 * b;
            const float4* q = (const float4*)p
                            + (size_t)(b * (NA * NCH) + a * NCH + 4) * HW4 + r;
            float4 v0 = q[0];
            float4 v1 = q[1];
            float lin = fmaxf(v0.x, 0.f) + fmaxf(v0.y, 0.f)
                      + fmaxf(v0.z, 0.f) + fmaxf(v0.w, 0.f)
                      + fmaxf(v1.x, 0.f) + fmaxf(v1.y, 0.f)
                      + fmaxf(v1.z, 0.f) + fmaxf(v1.w, 0.f);
            float prod = spl_factor(v0.x) * spl_factor(v0.y)
                       * spl_factor(v0.z) * spl_factor(v0.w)
                       * spl_factor(v1.x) * spl_factor(v1.y)
                       * spl_factor(v1.z) * spl_factor(v1.w);   // <= 2^8
            atomicAdd(&ssum[sc], lin + __logf(prod));
        }
        __syncthreads();
        if (t < 3 && ssum[t] != 0.f)
            atomicAdd(&g_obj_sum[t], (double)ssum[t]);
        __syncthreads();
    }

    // ---------------- device-side finalize (last block) ----------------
    if (t == 0) {
        __threadfence();
        unsigned old = atomicAdd(&g_done, 1u);
        if (old == gridDim.x - 1) {
            const double cnt[3] = {614400.0, 153600.0, 38400.0};
            double lod = 0.0;
            for (int s = 0; s < 3; s++)
                lod += (g_obj_sum[s] + (double)g_corr[s]) / cnt[s];
            const float lo = (float)lod;
            const float lb = g_box * (1.f / 2304.f);   // N*A*3
            const float lc = g_cls * (1.f / 2304.f);
            const float total = 0.05f * lb + 1.0f * lo + 0.5f * lc;
            float vals[5] = {total, lb, lo, lc, 0.f};
            for (int i = 0; i < out_size; i++)
                out[i] = (i < 5) ? vals[i] : 0.f;
            // reset for next graph replay
            g_box = 0.f;
            g_cls = 0.f;
            for (int s = 0; s < 3; s++) { g_corr[s] = 0.f; g_obj_sum[s] = 0.0; }
            g_done = 0u;
        }
    }
}

extern "C" void kernel_launch(void* const* d_in, const int* in_sizes, int n_in,
                              void* d_out, int out_size) {
    const float* p0 = (const float*)d_in[0];
    const float* p1 = (const float*)d_in[1];
    const float* p2 = (const float*)d_in[2];
    const float* tg = (const float*)d_in[3];
    (void)in_sizes; (void)n_in;

    // 9 target blocks + 394 sweep blocks (ceil(100800/256))
    fused_kernel<<<403, 256>>>(p0, p1, p2, tg, (float*)d_out, out_size);
}

// round 5
// speedup vs baseline: 1.3686x; 1.3198x over previous
#include <cuda_runtime.h>

#define NA   3
#define NC   20
#define NCH  25      // 5 + NC
#define NT   256     // number of targets
#define EPSF 1e-7f

// Accumulators. Zero-initialized at module load; the finalizing block
// re-zeroes them so every graph replay starts clean.
__device__ double   g_obj[3];
__device__ float    g_corr[3];
__device__ float    g_box;
__device__ float    g_cls;
__device__ unsigned g_done;

__device__ __forceinline__ float sigmoidf(float x) {
    return 1.f / (1.f + __expf(-x));
}
// factor (1 + e^x); product of a group, then one log = softplus group-sum
__device__ __forceinline__ float spf(float x) {
    return 1.f + __expf(x);
}

__device__ __forceinline__ float warpReduceSum(float v) {
    #pragma unroll
    for (int o = 16; o > 0; o >>= 1)
        v += __shfl_xor_sync(0xffffffffu, v, o);
    return v;
}

__global__ void __launch_bounds__(256) fused_kernel(
    const float* __restrict__ p0,
    const float* __restrict__ p1,
    const float* __restrict__ p2,
    const float* __restrict__ tg,
    float* __restrict__ out, int out_size)
{
    const int bid = blockIdx.x;
    const int t   = threadIdx.x;
    const int lid = t & 31;

    if (bid < 9) {
        // ---------------- target blocks: (scale, anchor) ----------------
        __shared__ float s_t[NT * 6];
        __shared__ int   s_key[NT];
        for (int i = t; i < NT * 6; i += 256) s_t[i] = tg[i];
        __syncthreads();

        const int s = bid / 3;
        const int a = bid - 3 * s;
        const int H  = (s == 0) ? 80 : (s == 1) ? 40 : 20;
        const int W  = H;
        const int HW = H * W;
        const float* p = (s == 0) ? p0 : (s == 1) ? p1 : p2;
        const float fw = (float)W, fh = (float)H;

        const int n = t;  // one thread per target
        const int   bi = (int)s_t[n * 6 + 0];
        const int   ci = (int)s_t[n * 6 + 1];
        const float cx = s_t[n * 6 + 2];
        const float cy = s_t[n * 6 + 3];
        const float tw = s_t[n * 6 + 4];
        const float th = s_t[n * 6 + 5];

        const int gi = (int)fminf(fmaxf(cx * fw, 0.f), fw - 1.f);
        const int gj = (int)fminf(fmaxf(cy * fh, 0.f), fh - 1.f);
        const int key = (bi << 14) | (gj << 7) | gi;
        s_key[n] = key;

        const float* cellp = p + ((size_t)(bi * NA * NCH + a * NCH)) * HW
                               + (size_t)gj * W + gi;

        const float sx = sigmoidf(cellp[0]);
        const float sy = sigmoidf(cellp[HW]);

        const float twh = tw * fw * 0.5f;
        const float thh = th * fh * 0.5f;
        const float gif = (float)gi, gjf = (float)gj;

        const float px1 = (sx + gif - twh) / fw;
        const float py1 = (sy + gjf - thh) / fh;
        const float px2 = (sx + gif + twh) / fw;
        const float py2 = (sy + gjf + thh) / fh;

        const float tx1 = cx - tw * 0.5f;
        const float ty1 = cy - th * 0.5f;
        const float tx2 = cx + tw * 0.5f;
        const float ty2 = cy + th * 0.5f;

        // CIoU loss
        const float ix1 = fmaxf(px1, tx1), iy1 = fmaxf(py1, ty1);
        const float ix2 = fminf(px2, tx2), iy2 = fminf(py2, ty2);
        const float inter  = fmaxf(ix2 - ix1, 0.f) * fmaxf(iy2 - iy1, 0.f);
        const float area_p = (px2 - px1) * (py2 - py1);
        const float area_t = (tx2 - tx1) * (ty2 - ty1);
        const float uni = area_p + area_t - inter + EPSF;
        const float iou = inter / uni;
        const float ex1 = fminf(px1, tx1), ey1 = fminf(py1, ty1);
        const float ex2 = fmaxf(px2, tx2), ey2 = fmaxf(py2, ty2);
        const float c2  = (ex2 - ex1) * (ex2 - ex1) + (ey2 - ey1) * (ey2 - ey1) + EPSF;
        const float dxc = (px1 + px2) * 0.5f - (tx1 + tx2) * 0.5f;
        const float dyc = (py1 + py2) * 0.5f - (ty1 + ty2) * 0.5f;
        const float rho2 = dxc * dxc + dyc * dyc;
        const float pw  = fmaxf(px2 - px1, EPSF);
        const float ph  = fmaxf(py2 - py1, EPSF);
        const float twc = fmaxf(tx2 - tx1, EPSF);
        const float thc = fmaxf(ty2 - ty1, EPSF);
        const float dd  = atanf(twc / thc) - atanf(pw / ph);
        const float v   = 0.4052847345693511f * dd * dd;   // 4/pi^2
        const float alpha = v / (1.f - iou + v + EPSF);
        const float lbox  = 1.f - (iou - rho2 / c2 - alpha * v);

        // cls BCE: [log prod(1+e^x) - x_ci] / NC
        float pr0 = 1.f, pr1 = 1.f;
        #pragma unroll
        for (int c = 0; c < NC; c += 2) {
            pr0 *= spf(cellp[(size_t)(5 + c) * HW]);
            pr1 *= spf(cellp[(size_t)(6 + c) * HW]);
        }
        float csum = (__logf(pr0 * pr1) - cellp[(size_t)(5 + ci) * HW])
                   * (1.f / (float)NC);

        __syncthreads();   // s_key ready

        // obj correction: -x for each UNIQUE target cell, all 3 anchors.
        float corr = 0.f;
        if (a == 0) {
            bool uniq = true;
            for (int m = 0; m < n; m++)
                if (s_key[m] == key) { uniq = false; break; }
            if (uniq) {
                const float* op = p + ((size_t)(bi * NA * NCH)) * HW
                                    + (size_t)gj * W + gi;
                corr = -(op[(size_t)4 * HW]
                       + op[(size_t)(NCH + 4) * HW]
                       + op[(size_t)(2 * NCH + 4) * HW]);
            }
        }

        float rb = warpReduceSum(lbox);
        float rc = warpReduceSum(csum);
        float ro = warpReduceSum(corr);
        if (lid == 0) {
            atomicAdd(&g_box, rb);
            atomicAdd(&g_cls, rc);
            if (a == 0) atomicAdd(&g_corr[s], ro);
            __threadfence();   // order my REDs before the barrier
        }
        __syncthreads();       // ALL warps' atomics fenced before finalize
    } else {
        // -------- objectness softplus sweep: 8 elems (2 float4) / thread --------
        // static per-scale block ranges: [9,309) sc0, [309,384) sc1, [384,403) sc2
        int sc, e8cap, HW4;
        const float* p;
        int base;
        if (bid < 309)      { sc = 0; p = p0; base = (bid - 9)   * 256; e8cap = 76800; HW4 = 1600; }
        else if (bid < 384) { sc = 1; p = p1; base = (bid - 309) * 256; e8cap = 19200; HW4 = 400;  }
        else                { sc = 2; p = p2; base = (bid - 384) * 256; e8cap = 4800;  HW4 = 100;  }

        const int e8 = base + t;
        float gsum = 0.f;
        if (e8 < e8cap) {
            const int f4    = e8 * 2;
            const int plane = f4 / HW4;          // pair never straddles a plane
            // channel offset: (25*plane + 4)*HW4 + (f4 - plane*HW4)
            //             =  f4 + HW4*(24*plane + 4)
            const float4* q = (const float4*)p + f4 + (size_t)HW4 * (24 * plane + 4);
            float4 v0 = q[0];
            float4 v1 = q[1];
            float f0 = spf(v0.x), f1 = spf(v0.y), f2 = spf(v0.z), f3 = spf(v0.w);
            float f4a = spf(v1.x), f5 = spf(v1.y), f6 = spf(v1.z), f7 = spf(v1.w);
            float prod = ((f0 * f1) * (f2 * f3)) * ((f4a * f5) * (f6 * f7));
            gsum = __logf(prod);
        }
        float wsum = warpReduceSum(gsum);
        if (lid == 0 && wsum != 0.f) {
            atomicAdd(&g_obj[sc], (double)wsum);
            __threadfence();
        }
        __syncthreads();
    }

    // ---------------- device-side finalize (last block) ----------------
    if (t == 0) {
        __threadfence();
        unsigned old = atomicAdd(&g_done, 1u);
        if (old == gridDim.x - 1) {
            const double cnt[3] = {614400.0, 153600.0, 38400.0};
            double lod = 0.0;
            for (int s = 0; s < 3; s++)
                lod += (g_obj[s] + (double)g_corr[s]) / cnt[s];
            const float lo = (float)lod;
            const float lb = g_box * (1.f / 2304.f);   // N*A*3
            const float lc = g_cls * (1.f / 2304.f);
            const float total = 0.05f * lb + 1.0f * lo + 0.5f * lc;
            float vals[5] = {total, lb, lo, lc, 0.f};
            for (int i = 0; i < out_size; i++)
                out[i] = (i < 5) ? vals[i] : 0.f;
            // reset for next graph replay
            g_box = 0.f;
            g_cls = 0.f;
            for (int s = 0; s < 3; s++) { g_corr[s] = 0.f; g_obj[s] = 0.0; }
            g_done = 0u;
        }
    }
}

extern "C" void kernel_launch(void* const* d_in, const int* in_sizes, int n_in,
                              void* d_out, int out_size) {
    const float* p0 = (const float*)d_in[0];
    const float* p1 = (const float*)d_in[1];
    const float* p2 = (const float*)d_in[2];
    const float* tg = (const float*)d_in[3];
    (void)in_sizes; (void)n_in;

    // 9 target blocks + 300 + 75 + 19 sweep blocks
    fused_kernel<<<403, 256>>>(p0, p1, p2, tg, (float*)d_out, out_size);
}

// round 6
// speedup vs baseline: 2.6250x; 1.9180x over previous
#include <cuda_runtime.h>

#define NA   3
#define NC   20
#define NCH  25      // 5 + NC
#define NT   256     // number of targets
#define EPSF 1e-7f

// Accumulators. Zero-initialized at module load; the finalizing block
// re-zeroes them so every graph replay starts clean.
__device__ double   g_obj[3];
__device__ float    g_corr[3];
__device__ float    g_box;
__device__ float    g_cls;
__device__ unsigned g_done;

__device__ __forceinline__ float sigmoidf(float x) {
    return 1.f / (1.f + __expf(-x));
}
// factor (1 + e^x); product of a group, then one log = softplus group-sum
__device__ __forceinline__ float spf(float x) {
    return 1.f + __expf(x);
}

__device__ __forceinline__ float warpReduceSum(float v) {
    #pragma unroll
    for (int o = 16; o > 0; o >>= 1)
        v += __shfl_xor_sync(0xffffffffu, v, o);
    return v;
}

// 16-element softplus group-sum, HW4 = HW/4 compile-time for cheap division
template<int HW4>
__device__ __forceinline__ float sweep16(const float* __restrict__ p, int e16) {
    const int f4    = e16 * 4;
    const int plane = f4 / HW4;                 // constant divisor -> mul/shift
    const float4* q = (const float4*)p + f4 + (size_t)HW4 * (24 * plane + 4);
    float4 v0 = q[0], v1 = q[1], v2 = q[2], v3 = q[3];   // MLP = 4
    float pa = (spf(v0.x) * spf(v0.y)) * (spf(v0.z) * spf(v0.w));
    float pb = (spf(v1.x) * spf(v1.y)) * (spf(v1.z) * spf(v1.w));
    float pc = (spf(v2.x) * spf(v2.y)) * (spf(v2.z) * spf(v2.w));
    float pd = (spf(v3.x) * spf(v3.y)) * (spf(v3.z) * spf(v3.w));
    return __logf(pa * pb) + __logf(pc * pd);   // two logs: overflow headroom
}

__global__ void __launch_bounds__(256) fused_kernel(
    const float* __restrict__ p0,
    const float* __restrict__ p1,
    const float* __restrict__ p2,
    const float* __restrict__ tg,
    float* __restrict__ out, int out_size)
{
    const int bid = blockIdx.x;
    const int t   = threadIdx.x;
    const int lid = t & 31;

    if (bid < 9) {
        // ---------------- target blocks: (scale, anchor) ----------------
        __shared__ float s_t[NT * 6];
        __shared__ int   s_key[NT];
        for (int i = t; i < NT * 6; i += 256) s_t[i] = tg[i];
        __syncthreads();

        const int s = bid / 3;
        const int a = bid - 3 * s;
        const int H  = (s == 0) ? 80 : (s == 1) ? 40 : 20;
        const int W  = H;
        const int HW = H * W;
        const float* p = (s == 0) ? p0 : (s == 1) ? p1 : p2;
        const float fw = (float)W, fh = (float)H;

        const int n = t;  // one thread per target
        const int   bi = (int)s_t[n * 6 + 0];
        const int   ci = (int)s_t[n * 6 + 1];
        const float cx = s_t[n * 6 + 2];
        const float cy = s_t[n * 6 + 3];
        const float tw = s_t[n * 6 + 4];
        const float th = s_t[n * 6 + 5];

        const int gi = (int)fminf(fmaxf(cx * fw, 0.f), fw - 1.f);
        const int gj = (int)fminf(fmaxf(cy * fh, 0.f), fh - 1.f);
        const int key = (bi << 14) | (gj << 7) | gi;
        s_key[n] = key;

        const float* cellp = p + ((size_t)(bi * NA * NCH + a * NCH)) * HW
                               + (size_t)gj * W + gi;

        // ---- issue ALL scattered loads up front (high MLP) ----
        const float x0 = cellp[0];
        const float x1 = cellp[HW];
        float xv[NC];
        #pragma unroll
        for (int c = 0; c < NC; c++) xv[c] = cellp[(size_t)(5 + c) * HW];
        const float xci = cellp[(size_t)(5 + ci) * HW];
        // obj-correction loads (block-uniform branch; zeroed later if dup)
        float c0 = 0.f, c1 = 0.f, c2v = 0.f;
        const float* op = p + ((size_t)(bi * NA * NCH)) * HW + (size_t)gj * W + gi;
        if (a == 0) {
            c0 = op[(size_t)4 * HW];
            c1 = op[(size_t)(NCH + 4) * HW];
            c2v = op[(size_t)(2 * NCH + 4) * HW];
        }

        const float sx = sigmoidf(x0);
        const float sy = sigmoidf(x1);

        const float twh = tw * fw * 0.5f;
        const float thh = th * fh * 0.5f;
        const float gif = (float)gi, gjf = (float)gj;

        const float px1 = (sx + gif - twh) / fw;
        const float py1 = (sy + gjf - thh) / fh;
        const float px2 = (sx + gif + twh) / fw;
        const float py2 = (sy + gjf + thh) / fh;

        const float tx1 = cx - tw * 0.5f;
        const float ty1 = cy - th * 0.5f;
        const float tx2 = cx + tw * 0.5f;
        const float ty2 = cy + th * 0.5f;

        // CIoU loss
        const float ix1 = fmaxf(px1, tx1), iy1 = fmaxf(py1, ty1);
        const float ix2 = fminf(px2, tx2), iy2 = fminf(py2, ty2);
        const float inter  = fmaxf(ix2 - ix1, 0.f) * fmaxf(iy2 - iy1, 0.f);
        const float area_p = (px2 - px1) * (py2 - py1);
        const float area_t = (tx2 - tx1) * (ty2 - ty1);
        const float uni = area_p + area_t - inter + EPSF;
        const float iou = inter / uni;
        const float ex1 = fminf(px1, tx1), ey1 = fminf(py1, ty1);
        const float ex2 = fmaxf(px2, tx2), ey2 = fmaxf(py2, ty2);
        const float c2  = (ex2 - ex1) * (ex2 - ex1) + (ey2 - ey1) * (ey2 - ey1) + EPSF;
        const float dxc = (px1 + px2) * 0.5f - (tx1 + tx2) * 0.5f;
        const float dyc = (py1 + py2) * 0.5f - (ty1 + ty2) * 0.5f;
        const float rho2 = dxc * dxc + dyc * dyc;
        const float pw  = fmaxf(px2 - px1, EPSF);
        const float ph  = fmaxf(py2 - py1, EPSF);
        const float twc = fmaxf(tx2 - tx1, EPSF);
        const float thc = fmaxf(ty2 - ty1, EPSF);
        const float dd  = atanf(twc / thc) - atanf(pw / ph);
        const float v   = 0.4052847345693511f * dd * dd;   // 4/pi^2
        const float alpha = v / (1.f - iou + v + EPSF);
        const float lbox  = 1.f - (iou - rho2 / c2 - alpha * v);

        // cls BCE: [log prod(1+e^x) - x_ci] / NC  (4-way ILP product)
        float pr0 = 1.f, pr1 = 1.f, pr2 = 1.f, pr3 = 1.f;
        #pragma unroll
        for (int c = 0; c < NC; c += 4) {
            pr0 *= spf(xv[c]);
            pr1 *= spf(xv[c + 1]);
            pr2 *= spf(xv[c + 2]);
            pr3 *= spf(xv[c + 3]);
        }
        float csum = (__logf((pr0 * pr1) * (pr2 * pr3)) - xci) * (1.f / (float)NC);

        __syncthreads();   // s_key ready

        // uniqueness: no early break -> LDS batches; OR-accumulate
        float corr = 0.f;
        if (a == 0) {
            bool dup = false;
            #pragma unroll 4
            for (int m = 0; m < n; m++)
                dup |= (s_key[m] == key);
            corr = dup ? 0.f : -(c0 + c1 + c2v);
        }

        float rb = warpReduceSum(lbox);
        float rc = warpReduceSum(csum);
        float ro = warpReduceSum(corr);
        if (lid == 0) {
            atomicAdd(&g_box, rb);
            atomicAdd(&g_cls, rc);
            if (a == 0) atomicAdd(&g_corr[s], ro);
            __threadfence();   // order my REDs before the barrier
        }
        __syncthreads();       // ALL warps' atomics fenced before finalize
    } else {
        // -------- objectness softplus sweep: 16 elems (4 float4) / thread --------
        // block ranges: [9,159) sc0, [159,197) sc1, [197,207) sc2
        float gsum = 0.f;
        double* acc;
        if (bid < 159) {
            const int e16 = (bid - 9) * 256 + t;          // cap 38400: exact
            gsum = sweep16<1600>(p0, e16);
            acc = &g_obj[0];
        } else if (bid < 197) {
            const int e16 = (bid - 159) * 256 + t;
            if (e16 < 9600) gsum = sweep16<400>(p1, e16);
            acc = &g_obj[1];
        } else {
            const int e16 = (bid - 197) * 256 + t;
            if (e16 < 2400) gsum = sweep16<100>(p2, e16);
            acc = &g_obj[2];
        }
        float wsum = warpReduceSum(gsum);
        if (lid == 0 && wsum != 0.f) {
            atomicAdd(acc, (double)wsum);
            __threadfence();
        }
        __syncthreads();
    }

    // ---------------- device-side finalize (last block) ----------------
    if (t == 0) {
        __threadfence();
        unsigned old = atomicAdd(&g_done, 1u);
        if (old == gridDim.x - 1) {
            const double cnt[3] = {614400.0, 153600.0, 38400.0};
            double lod = 0.0;
            for (int s = 0; s < 3; s++)
                lod += (g_obj[s] + (double)g_corr[s]) / cnt[s];
            const float lo = (float)lod;
            const float lb = g_box * (1.f / 2304.f);   // N*A*3
            const float lc = g_cls * (1.f / 2304.f);
            const float total = 0.05f * lb + 1.0f * lo + 0.5f * lc;
            float vals[5] = {total, lb, lo, lc, 0.f};
            for (int i = 0; i < out_size; i++)
                out[i] = (i < 5) ? vals[i] : 0.f;
            // reset for next graph replay
            g_box = 0.f;
            g_cls = 0.f;
            for (int s = 0; s < 3; s++) { g_corr[s] = 0.f; g_obj[s] = 0.0; }
            g_done = 0u;
        }
    }
}

extern "C" void kernel_launch(void* const* d_in, const int* in_sizes, int n_in,
                              void* d_out, int out_size) {
    const float* p0 = (const float*)d_in[0];
    const float* p1 = (const float*)d_in[1];
    const float* p2 = (const float*)d_in[2];
    const float* tg = (const float*)d_in[3];
    (void)in_sizes; (void)n_in;

    // 9 target blocks + 150 + 38 + 10 sweep blocks
    fused_kernel<<<207, 256>>>(p0, p1, p2, tg, (float*)d_out, out_size);
}

// round 8
// speedup vs baseline: 2.8966x; 1.1034x over previous
#include <cuda_runtime.h>

#define NA   3
#define NC   20
#define NCH  25      // 5 + NC
#define NT   256     // number of targets
#define EPSF 1e-7f

// Accumulators. Zero-initialized at module load; the finalizing block
// re-zeroes them so every graph replay starts clean.
__device__ double   g_obj[3];
__device__ float    g_corr[3];
__device__ float    g_box;
__device__ float    g_cls;
__device__ unsigned g_done;

__device__ __forceinline__ float sigmoidf(float x) {
    return 1.f / (1.f + __expf(-x));
}
// factor (1 + e^x); product of a group, then one log = softplus group-sum
__device__ __forceinline__ float spf(float x) {
    return 1.f + __expf(x);
}

__device__ __forceinline__ float warpReduceSum(float v) {
    #pragma unroll
    for (int o = 16; o > 0; o >>= 1)
        v += __shfl_xor_sync(0xffffffffu, v, o);
    return v;
}

__device__ __forceinline__ float prod8(float4 a, float4 b) {
    return ((spf(a.x) * spf(a.y)) * (spf(a.z) * spf(a.w)))
         * ((spf(b.x) * spf(b.y)) * (spf(b.z) * spf(b.w)));
}

// 32-element softplus group-sum; requires HW4 % 8 == 0 (no plane straddle)
template<int HW4>
__device__ __forceinline__ float sweep32(const float* __restrict__ p, int e32) {
    const int f4    = e32 * 8;
    const int plane = f4 / HW4;                 // constant divisor -> mul/shift
    const float4* q = (const float4*)p + f4 + (size_t)HW4 * (24 * plane + 4);
    // 8 independent loads issued back-to-back: MLP = 8
    float4 v0 = q[0], v1 = q[1], v2 = q[2], v3 = q[3];
    float4 v4 = q[4], v5 = q[5], v6 = q[6], v7 = q[7];
    float pa = prod8(v0, v1);    // each product of 8 factors <= ~1e21, safe
    float pb = prod8(v2, v3);
    float pc = prod8(v4, v5);
    float pd = prod8(v6, v7);
    return (__logf(pa) + __logf(pb)) + (__logf(pc) + __logf(pd));
}

// 16-element variant for scale 2 (HW4 = 100, multiple of 4 only)
template<int HW4>
__device__ __forceinline__ float sweep16(const float* __restrict__ p, int e16) {
    const int f4    = e16 * 4;
    const int plane = f4 / HW4;
    const float4* q = (const float4*)p + f4 + (size_t)HW4 * (24 * plane + 4);
    float4 v0 = q[0], v1 = q[1], v2 = q[2], v3 = q[3];
    return __logf(prod8(v0, v1)) + __logf(prod8(v2, v3));
}

__global__ void __launch_bounds__(256) fused_kernel(
    const float* __restrict__ p0,
    const float* __restrict__ p1,
    const float* __restrict__ p2,
    const float* __restrict__ tg,
    float* __restrict__ out, int out_size)
{
    const int bid = blockIdx.x;
    const int t   = threadIdx.x;
    const int lid = t & 31;

    if (bid < 9) {
        // ---------------- target blocks: (scale, anchor) ----------------
        __shared__ float s_t[NT * 6];
        __shared__ int   s_key[NT];
        for (int i = t; i < NT * 6; i += 256) s_t[i] = tg[i];
        __syncthreads();

        const int s = bid / 3;
        const int a = bid - 3 * s;
        const int H  = (s == 0) ? 80 : (s == 1) ? 40 : 20;
        const int W  = H;
        const int HW = H * W;
        const float* p = (s == 0) ? p0 : (s == 1) ? p1 : p2;
        const float fw = (float)W, fh = (float)H;

        const int n = t;  // one thread per target
        const int   bi = (int)s_t[n * 6 + 0];
        const int   ci = (int)s_t[n * 6 + 1];
        const float cx = s_t[n * 6 + 2];
        const float cy = s_t[n * 6 + 3];
        const float tw = s_t[n * 6 + 4];
        const float th = s_t[n * 6 + 5];

        const int gi = (int)fminf(fmaxf(cx * fw, 0.f), fw - 1.f);
        const int gj = (int)fminf(fmaxf(cy * fh, 0.f), fh - 1.f);
        const int key = (bi << 14) | (gj << 7) | gi;
        s_key[n] = key;

        const float* cellp = p + ((size_t)(bi * NA * NCH + a * NCH)) * HW
                               + (size_t)gj * W + gi;

        // ---- issue ALL scattered loads up front (high MLP) ----
        const float x0 = cellp[0];
        const float x1 = cellp[HW];
        float xv[NC];
        #pragma unroll
        for (int c = 0; c < NC; c++) xv[c] = cellp[(size_t)(5 + c) * HW];
        const float xci = cellp[(size_t)(5 + ci) * HW];
        // obj-correction loads (block-uniform branch; zeroed later if dup)
        float c0 = 0.f, c1 = 0.f, c2v = 0.f;
        const float* op = p + ((size_t)(bi * NA * NCH)) * HW + (size_t)gj * W + gi;
        if (a == 0) {
            c0 = op[(size_t)4 * HW];
            c1 = op[(size_t)(NCH + 4) * HW];
            c2v = op[(size_t)(2 * NCH + 4) * HW];
        }

        const float sx = sigmoidf(x0);
        const float sy = sigmoidf(x1);

        const float twh = tw * fw * 0.5f;
        const float thh = th * fh * 0.5f;
        const float gif = (float)gi, gjf = (float)gj;

        const float px1 = (sx + gif - twh) / fw;
        const float py1 = (sy + gjf - thh) / fh;
        const float px2 = (sx + gif + twh) / fw;
        const float py2 = (sy + gjf + thh) / fh;

        const float tx1 = cx - tw * 0.5f;
        const float ty1 = cy - th * 0.5f;
        const float tx2 = cx + tw * 0.5f;
        const float ty2 = cy + th * 0.5f;

        // CIoU loss
        const float ix1 = fmaxf(px1, tx1), iy1 = fmaxf(py1, ty1);
        const float ix2 = fminf(px2, tx2), iy2 = fminf(py2, ty2);
        const float inter  = fmaxf(ix2 - ix1, 0.f) * fmaxf(iy2 - iy1, 0.f);
        const float area_p = (px2 - px1) * (py2 - py1);
        const float area_t = (tx2 - tx1) * (ty2 - ty1);
        const float uni = area_p + area_t - inter + EPSF;
        const float iou = inter / uni;
        const float ex1 = fminf(px1, tx1), ey1 = fminf(py1, ty1);
        const float ex2 = fmaxf(px2, tx2), ey2 = fmaxf(py2, ty2);
        const float c2  = (ex2 - ex1) * (ex2 - ex1) + (ey2 - ey1) * (ey2 - ey1) + EPSF;
        const float dxc = (px1 + px2) * 0.5f - (tx1 + tx2) * 0.5f;
        const float dyc = (py1 + py2) * 0.5f - (ty1 + ty2) * 0.5f;
        const float rho2 = dxc * dxc + dyc * dyc;
        const float pw  = fmaxf(px2 - px1, EPSF);
        const float ph  = fmaxf(py2 - py1, EPSF);
        const float twc = fmaxf(tx2 - tx1, EPSF);
        const float thc = fmaxf(ty2 - ty1, EPSF);
        const float dd  = atanf(twc / thc) - atanf(pw / ph);
        const float v   = 0.4052847345693511f * dd * dd;   // 4/pi^2
        const float alpha = v / (1.f - iou + v + EPSF);
        const float lbox  = 1.f - (iou - rho2 / c2 - alpha * v);

        // cls BCE: [log prod(1+e^x) - x_ci] / NC  (4-way ILP product)
        float pr0 = 1.f, pr1 = 1.f, pr2 = 1.f, pr3 = 1.f;
        #pragma unroll
        for (int c = 0; c < NC; c += 4) {
            pr0 *= spf(xv[c]);
            pr1 *= spf(xv[c + 1]);
            pr2 *= spf(xv[c + 2]);
            pr3 *= spf(xv[c + 3]);
        }
        float csum = (__logf((pr0 * pr1) * (pr2 * pr3)) - xci) * (1.f / (float)NC);

        __syncthreads();   // s_key ready

        // uniqueness: no early break -> LDS batches; OR-accumulate
        float corr = 0.f;
        if (a == 0) {
            bool dup = false;
            #pragma unroll 4
            for (int m = 0; m < n; m++)
                dup |= (s_key[m] == key);
            corr = dup ? 0.f : -(c0 + c1 + c2v);
        }

        float rb = warpReduceSum(lbox);
        float rc = warpReduceSum(csum);
        float ro = warpReduceSum(corr);
        if (lid == 0) {
            atomicAdd(&g_box, rb);
            atomicAdd(&g_cls, rc);
            if (a == 0) atomicAdd(&g_corr[s], ro);
            __threadfence();   // order my REDs before the barrier
        }
        __syncthreads();       // ALL warps' atomics fenced before finalize
    } else {
        // -------- objectness softplus sweep --------
        // block ranges: [9,84) sc0 (32/thr), [84,103) sc1 (32/thr), [103,113) sc2 (16/thr)
        float gsum = 0.f;
        double* acc;
        if (bid < 84) {
            const int e32 = (bid - 9) * 256 + t;          // cap 19200: exact (75 blocks)
            gsum = sweep32<1600>(p0, e32);
            acc = &g_obj[0];
        } else if (bid < 103) {
            const int e32 = (bid - 84) * 256 + t;         // cap 4800
            if (e32 < 4800) gsum = sweep32<400>(p1, e32);
            acc = &g_obj[1];
        } else {
            const int e16 = (bid - 103) * 256 + t;        // cap 2400
            if (e16 < 2400) gsum = sweep16<100>(p2, e16);
            acc = &g_obj[2];
        }
        float wsum = warpReduceSum(gsum);
        if (lid == 0 && wsum != 0.f) {
            atomicAdd(acc, (double)wsum);
            __threadfence();
        }
        __syncthreads();
    }

    // ---------------- device-side finalize (last block) ----------------
    if (t == 0) {
        __threadfence();
        unsigned old = atomicAdd(&g_done, 1u);
        if (old == gridDim.x - 1) {
            const double cnt[3] = {614400.0, 153600.0, 38400.0};
            double lod = 0.0;
            for (int s = 0; s < 3; s++)
                lod += (g_obj[s] + (double)g_corr[s]) / cnt[s];
            const float lo = (float)lod;
            const float lb = g_box * (1.f / 2304.f);   // N*A*3
            const float lc = g_cls * (1.f / 2304.f);
            const float total = 0.05f * lb + 1.0f * lo + 0.5f * lc;
            float vals[5] = {total, lb, lo, lc, 0.f};
            for (int i = 0; i < out_size; i++)
                out[i] = (i < 5) ? vals[i] : 0.f;
            // reset for next graph replay
            g_box = 0.f;
            g_cls = 0.f;
            for (int s = 0; s < 3; s++) { g_corr[s] = 0.f; g_obj[s] = 0.0; }
            g_done = 0u;
        }
    }
}

extern "C" void kernel_launch(void* const* d_in, const int* in_sizes, int n_in,
                              void* d_out, int out_size) {
    const float* p0 = (const float*)d_in[0];
    const float* p1 = (const float*)d_in[1];
    const float* p2 = (const float*)d_in[2];
    const float* tg = (const float*)d_in[3];
    (void)in_sizes; (void)n_in;

    // 9 target + 75 + 19 + 10 sweep = 113 blocks: one wave, <=1 block/SM
    fused_kernel<<<113, 256>>>(p0, p1, p2, tg, (float*)d_out, out_size);
}

// round 9
// speedup vs baseline: 3.3684x; 1.1629x over previous
#include <cuda_runtime.h>

#define NA   3
#define NC   20
#define NCH  25      // 5 + NC
#define NT   256     // number of targets
#define TPB  64      // targets per target-block (NT/4)
#define EPSF 1e-7f

// Accumulators. Zero-initialized at module load; the finalizing block
// re-zeroes them so every graph replay starts clean.
__device__ double   g_obj[3];
__device__ float    g_corr[3];
__device__ float    g_box;
__device__ float    g_cls;
__device__ unsigned g_done;

__device__ __forceinline__ float sigmoidf(float x) {
    return 1.f / (1.f + __expf(-x));
}
// factor (1 + e^x); product of a group, then one log = softplus group-sum
__device__ __forceinline__ float spf(float x) {
    return 1.f + __expf(x);
}

__device__ __forceinline__ float warpReduceSum(float v) {
    #pragma unroll
    for (int o = 16; o > 0; o >>= 1)
        v += __shfl_xor_sync(0xffffffffu, v, o);
    return v;
}

__device__ __forceinline__ float prod8(float4 a, float4 b) {
    return ((spf(a.x) * spf(a.y)) * (spf(a.z) * spf(a.w)))
         * ((spf(b.x) * spf(b.y)) * (spf(b.z) * spf(b.w)));
}

// 32-element softplus group-sum; requires HW4 % 8 == 0 (no plane straddle)
template<int HW4>
__device__ __forceinline__ float sweep32(const float* __restrict__ p, int e32) {
    const int f4    = e32 * 8;
    const int plane = f4 / HW4;                 // constant divisor -> mul/shift
    const float4* q = (const float4*)p + f4 + (size_t)HW4 * (24 * plane + 4);
    float4 v0 = q[0], v1 = q[1], v2 = q[2], v3 = q[3];
    float4 v4 = q[4], v5 = q[5], v6 = q[6], v7 = q[7];   // MLP = 8
    float pa = prod8(v0, v1);    // each product of 8 factors <= ~1e21, safe
    float pb = prod8(v2, v3);
    float pc = prod8(v4, v5);
    float pd = prod8(v6, v7);
    return (__logf(pa) + __logf(pb)) + (__logf(pc) + __logf(pd));
}

// 16-element variant for scale 2 (HW4 = 100, multiple of 4 only)
template<int HW4>
__device__ __forceinline__ float sweep16(const float* __restrict__ p, int e16) {
    const int f4    = e16 * 4;
    const int plane = f4 / HW4;
    const float4* q = (const float4*)p + f4 + (size_t)HW4 * (24 * plane + 4);
    float4 v0 = q[0], v1 = q[1], v2 = q[2], v3 = q[3];
    return __logf(prod8(v0, v1)) + __logf(prod8(v2, v3));
}

__global__ void __launch_bounds__(256) fused_kernel(
    const float* __restrict__ p0,
    const float* __restrict__ p1,
    const float* __restrict__ p2,
    const float* __restrict__ tg,
    float* __restrict__ out, int out_size)
{
    const int bid = blockIdx.x;
    const int t   = threadIdx.x;
    const int lid = t & 31;

    if (bid < 36) {
        // ------- target blocks: (scale, anchor, quarter), 64 targets each -------
        __shared__ float s_t[NT * 6];
        __shared__ int   s_key[NT];
        for (int i = t; i < NT * 6; i += 256) s_t[i] = tg[i];
        __syncthreads();

        const int s = bid / 12;                 // scale
        const int a = (bid / 4) % 3;            // anchor
        const int q4 = bid & 3;                 // quarter
        const int H  = (s == 0) ? 80 : (s == 1) ? 40 : 20;
        const int W  = H;
        const int HW = H * W;
        const float* p = (s == 0) ? p0 : (s == 1) ? p1 : p2;
        const float fw = (float)W, fh = (float)H;

        // every thread computes the key for target t (full table for dedup scan)
        {
            const int   kb = (int)s_t[t * 6 + 0];
            const float kx = s_t[t * 6 + 2];
            const float ky = s_t[t * 6 + 3];
            const int kgi = (int)fminf(fmaxf(kx * fw, 0.f), fw - 1.f);
            const int kgj = (int)fminf(fmaxf(ky * fh, 0.f), fh - 1.f);
            s_key[t] = (kb << 14) | (kgj << 7) | kgi;
        }
        __syncthreads();

        float lbox = 0.f, csum = 0.f, corr = 0.f;
        if (t < TPB) {
            const int n = q4 * TPB + t;         // this thread's target
            const int   bi = (int)s_t[n * 6 + 0];
            const int   ci = (int)s_t[n * 6 + 1];
            const float cx = s_t[n * 6 + 2];
            const float cy = s_t[n * 6 + 3];
            const float tw = s_t[n * 6 + 4];
            const float th = s_t[n * 6 + 5];

            const int gi = (int)fminf(fmaxf(cx * fw, 0.f), fw - 1.f);
            const int gj = (int)fminf(fmaxf(cy * fh, 0.f), fh - 1.f);
            const int key = (bi << 14) | (gj << 7) | gi;

            const float* cellp = p + ((size_t)(bi * NA * NCH + a * NCH)) * HW
                                   + (size_t)gj * W + gi;

            // ---- issue ALL scattered loads up front (high MLP) ----
            const float x0 = cellp[0];
            const float x1 = cellp[HW];
            float xv[NC];
            #pragma unroll
            for (int c = 0; c < NC; c++) xv[c] = cellp[(size_t)(5 + c) * HW];
            const float xci = cellp[(size_t)(5 + ci) * HW];
            float c0 = 0.f, c1 = 0.f, c2v = 0.f;
            const float* op = p + ((size_t)(bi * NA * NCH)) * HW + (size_t)gj * W + gi;
            if (a == 0) {
                c0  = op[(size_t)4 * HW];
                c1  = op[(size_t)(NCH + 4) * HW];
                c2v = op[(size_t)(2 * NCH + 4) * HW];
            }

            const float sx = sigmoidf(x0);
            const float sy = sigmoidf(x1);

            const float twh = tw * fw * 0.5f;
            const float thh = th * fh * 0.5f;
            const float gif = (float)gi, gjf = (float)gj;

            const float px1 = (sx + gif - twh) / fw;
            const float py1 = (sy + gjf - thh) / fh;
            const float px2 = (sx + gif + twh) / fw;
            const float py2 = (sy + gjf + thh) / fh;

            const float tx1 = cx - tw * 0.5f;
            const float ty1 = cy - th * 0.5f;
            const float tx2 = cx + tw * 0.5f;
            const float ty2 = cy + th * 0.5f;

            // CIoU loss
            const float ix1 = fmaxf(px1, tx1), iy1 = fmaxf(py1, ty1);
            const float ix2 = fminf(px2, tx2), iy2 = fminf(py2, ty2);
            const float inter  = fmaxf(ix2 - ix1, 0.f) * fmaxf(iy2 - iy1, 0.f);
            const float area_p = (px2 - px1) * (py2 - py1);
            const float area_t = (tx2 - tx1) * (ty2 - ty1);
            const float uni = area_p + area_t - inter + EPSF;
            const float iou = inter / uni;
            const float ex1 = fminf(px1, tx1), ey1 = fminf(py1, ty1);
            const float ex2 = fmaxf(px2, tx2), ey2 = fmaxf(py2, ty2);
            const float c2  = (ex2 - ex1) * (ex2 - ex1) + (ey2 - ey1) * (ey2 - ey1) + EPSF;
            const float dxc = (px1 + px2) * 0.5f - (tx1 + tx2) * 0.5f;
            const float dyc = (py1 + py2) * 0.5f - (ty1 + ty2) * 0.5f;
            const float rho2 = dxc * dxc + dyc * dyc;
            const float pw  = fmaxf(px2 - px1, EPSF);
            const float ph  = fmaxf(py2 - py1, EPSF);
            const float twc = fmaxf(tx2 - tx1, EPSF);
            const float thc = fmaxf(ty2 - ty1, EPSF);
            const float dd  = atanf(twc / thc) - atanf(pw / ph);
            const float v   = 0.4052847345693511f * dd * dd;   // 4/pi^2
            const float alpha = v / (1.f - iou + v + EPSF);
            lbox = 1.f - (iou - rho2 / c2 - alpha * v);

            // cls BCE: [log prod(1+e^x) - x_ci] / NC  (4-way ILP product)
            float pr0 = 1.f, pr1 = 1.f, pr2 = 1.f, pr3 = 1.f;
            #pragma unroll
            for (int c = 0; c < NC; c += 4) {
                pr0 *= spf(xv[c]);
                pr1 *= spf(xv[c + 1]);
                pr2 *= spf(xv[c + 2]);
                pr3 *= spf(xv[c + 3]);
            }
            csum = (__logf((pr0 * pr1) * (pr2 * pr3)) - xci) * (1.f / (float)NC);

            // obj correction for first occurrence of this cell (all anchors)
            if (a == 0) {
                bool dup = false;
                #pragma unroll 4
                for (int m = 0; m < n; m++)
                    dup |= (s_key[m] == key);
                corr = dup ? 0.f : -(c0 + c1 + c2v);
            }
        }

        // warps 0-1 hold all contributions; others have zeros and skip atomics
        float rb = warpReduceSum(lbox);
        float rc = warpReduceSum(csum);
        float ro = warpReduceSum(corr);
        if (lid == 0 && t < TPB) {
            atomicAdd(&g_box, rb);
            atomicAdd(&g_cls, rc);
            if (a == 0) atomicAdd(&g_corr[s], ro);
            __threadfence();   // order my REDs before the barrier
        }
        __syncthreads();       // all warps' atomics fenced before finalize
    } else {
        // -------- objectness softplus sweep --------
        // block ranges: [36,111) sc0 (32/thr), [111,130) sc1 (32/thr), [130,140) sc2 (16/thr)
        float gsum = 0.f;
        double* acc;
        if (bid < 111) {
            const int e32 = (bid - 36) * 256 + t;         // cap 19200: exact (75 blocks)
            gsum = sweep32<1600>(p0, e32);
            acc = &g_obj[0];
        } else if (bid < 130) {
            const int e32 = (bid - 111) * 256 + t;        // cap 4800
            if (e32 < 4800) gsum = sweep32<400>(p1, e32);
            acc = &g_obj[1];
        } else {
            const int e16 = (bid - 130) * 256 + t;        // cap 2400
            if (e16 < 2400) gsum = sweep16<100>(p2, e16);
            acc = &g_obj[2];
        }
        float wsum = warpReduceSum(gsum);
        if (lid == 0 && wsum != 0.f) {
            atomicAdd(acc, (double)wsum);
            __threadfence();
        }
        __syncthreads();
    }

    // ---------------- device-side finalize (last block) ----------------
    if (t == 0) {
        __threadfence();
        unsigned old = atomicAdd(&g_done, 1u);
        if (old == gridDim.x - 1) {
            const double cnt[3] = {614400.0, 153600.0, 38400.0};
            double lod = 0.0;
            for (int s = 0; s < 3; s++)
                lod += (g_obj[s] + (double)g_corr[s]) / cnt[s];
            const float lo = (float)lod;
            const float lb = g_box * (1.f / 2304.f);   // N*A*3
            const float lc = g_cls * (1.f / 2304.f);
            const float total = 0.05f * lb + 1.0f * lo + 0.5f * lc;
            float vals[5] = {total, lb, lo, lc, 0.f};
            for (int i = 0; i < out_size; i++)
                out[i] = (i < 5) ? vals[i] : 0.f;
            // reset for next graph replay
            g_box = 0.f;
            g_cls = 0.f;
            for (int s = 0; s < 3; s++) { g_corr[s] = 0.f; g_obj[s] = 0.0; }
            g_done = 0u;
        }
    }
}

extern "C" void kernel_launch(void* const* d_in, const int* in_sizes, int n_in,
                              void* d_out, int out_size) {
    const float* p0 = (const float*)d_in[0];
    const float* p1 = (const float*)d_in[1];
    const float* p2 = (const float*)d_in[2];
    const float* tg = (const float*)d_in[3];
    (void)in_sizes; (void)n_in;

    // 36 target + 75 + 19 + 10 sweep = 140 blocks: one wave, <=1 block/SM
    fused_kernel<<<140, 256>>>(p0, p1, p2, tg, (float*)d_out, out_size);
}